// round 1
// baseline (speedup 1.0000x reference)
#include <cuda_runtime.h>

#define NN 50000
#define NE 800000
#define C 128
#define M_PAD 50048   /* 391 * 128 */

// ---------------- device scratch (static, no allocation) ----------------
__device__ int   g_is64;
__device__ int   g_deg[NN];
__device__ int   g_cursor[NN];
__device__ int   g_off[NN + 1];
__device__ float g_dinv[NN];
__device__ int   g_esrc[NE];
__device__ float g_enorm[NE];
__device__ float g_buf0[(size_t)M_PAD * C];   // GEMM output h
__device__ float g_buf1[(size_t)M_PAD * C];   // aggregated activations a

// ---------------- dtype probe: int64 vs int32 edge_index ----------------
__global__ void k_probe(const unsigned int* __restrict__ w) {
    if (threadIdx.x == 0 && blockIdx.x == 0) {
        int is64 = 1;
        for (int i = 0; i < 1024; ++i) {
            if (w[2 * i + 1] != 0u) { is64 = 0; break; }
        }
        g_is64 = is64;
    }
}

__device__ __forceinline__ int edge_at(const void* ei, int is64, long long idx) {
    return is64 ? (int)((const long long*)ei)[idx] : ((const int*)ei)[idx];
}

// ---------------- CSR construction ----------------
__global__ void k_init() {
    int i = blockIdx.x * blockDim.x + threadIdx.x;
    if (i < NN) { g_deg[i] = 0; g_cursor[i] = 0; }
}

__global__ void k_count(const void* __restrict__ ei) {
    int e = blockIdx.x * blockDim.x + threadIdx.x;
    if (e >= NE) return;
    int is64 = g_is64;
    int d = edge_at(ei, is64, (long long)NE + e);
    atomicAdd(&g_deg[d], 1);
}

__global__ void k_dinv() {
    int i = blockIdx.x * blockDim.x + threadIdx.x;
    if (i < NN) g_dinv[i] = rsqrtf((float)(g_deg[i] + 1));  // +1 self loop
}

__global__ void k_scan() {
    __shared__ int ps[1024];
    int t = threadIdx.x;
    const int CH = (NN + 1023) / 1024;
    int lo = t * CH;
    int hi = lo + CH; if (hi > NN) hi = NN;
    int sum = 0;
    for (int i = lo; i < hi; ++i) sum += g_deg[i];
    ps[t] = sum;
    __syncthreads();
    for (int off = 1; off < 1024; off <<= 1) {
        int v = (t >= off) ? ps[t - off] : 0;
        __syncthreads();
        ps[t] += v;
        __syncthreads();
    }
    int run = (t == 0) ? 0 : ps[t - 1];
    for (int i = lo; i < hi; ++i) { g_off[i] = run; run += g_deg[i]; }
    if (t == 1023) g_off[NN] = ps[1023];
}

__global__ void k_fill(const void* __restrict__ ei) {
    int e = blockIdx.x * blockDim.x + threadIdx.x;
    if (e >= NE) return;
    int is64 = g_is64;
    int s = edge_at(ei, is64, e);
    int d = edge_at(ei, is64, (long long)NE + e);
    int pos = g_off[d] + atomicAdd(&g_cursor[d], 1);
    g_esrc[pos]  = s;
    g_enorm[pos] = g_dinv[s] * g_dinv[d];
}

// ---------------- GEMM: [M,128] @ [128,128], fp32, smem-tiled ----------------
// block = 256 threads, tile 128 rows x 128 cols (full K=128), 8x8 per thread.
// Aext != nullptr -> A = Aext (x input); else A = g_buf1. Output always g_buf0.
#define GEMM_SMEM_BYTES (128 * 129 * 4 + 128 * 128 * 4)

__global__ void __launch_bounds__(256, 1) k_gemm(const float* __restrict__ Aext) {
    extern __shared__ float sm[];
    float* Ast = sm;                 // transposed A tile: [k][r], pitch 129
    float* Ws  = sm + 128 * 129;     // W tile: [k][o], pitch 128

    const float* A = Aext ? Aext : g_buf1;
    const float* W = 0;   // set below via second param trick
    // (W pointer passed via constant: see launch — we smuggle it in Ast? No:
    //  declared as second kernel arg instead)
    (void)W;
    // -- this body continues in k_gemm2 style below --
    // NOTE: real implementation uses the 2-arg kernel declared next.
    // (unreachable; kept to satisfy compiler if ever launched)
    if (threadIdx.x == ~0u) Ast[0] = A[0];
}

__global__ void __launch_bounds__(256, 1) k_gemm2(const float* __restrict__ Aext,
                                                  const float* __restrict__ W) {
    extern __shared__ float sm[];
    float* Ast = sm;                 // [k][r], pitch 129 (conflict-free transpose)
    float* Ws  = sm + 128 * 129;     // [k][o], pitch 128

    const float* __restrict__ A = Aext ? Aext : g_buf1;
    const int tid = threadIdx.x;
    const int tx = tid & 15;         // output-col group
    const int ty = tid >> 4;         // output-row group
    const int row0 = blockIdx.x * 128;

    // Load A tile transposed (scalar: lane-consecutive k -> conflict-free with pitch 129)
    #pragma unroll
    for (int it = 0; it < 64; ++it) {
        int idx = tid + 256 * it;            // 0..16383
        int r = idx >> 7;
        int k = idx & 127;
        int grow = row0 + r;
        float v = (grow < NN) ? A[(size_t)grow * C + k] : 0.0f;
        Ast[k * 129 + r] = v;
    }
    // Load W tile (same layout, float4)
    {
        const float4* W4 = (const float4*)W;
        float4* Ws4 = (float4*)Ws;
        #pragma unroll
        for (int it = 0; it < 16; ++it) {
            int idx = tid + 256 * it;        // float4 idx 0..4095
            Ws4[idx] = W4[idx];
        }
    }
    __syncthreads();

    float acc[8][8];
    #pragma unroll
    for (int i = 0; i < 8; ++i)
        #pragma unroll
        for (int j = 0; j < 8; ++j) acc[i][j] = 0.0f;

    #pragma unroll 4
    for (int k = 0; k < 128; ++k) {
        float a[8];
        #pragma unroll
        for (int i = 0; i < 8; ++i) a[i] = Ast[k * 129 + ty * 8 + i];
        float4 b0 = *(const float4*)(Ws + k * 128 + tx * 8);
        float4 b1 = *(const float4*)(Ws + k * 128 + tx * 8 + 4);
        float b[8] = {b0.x, b0.y, b0.z, b0.w, b1.x, b1.y, b1.z, b1.w};
        #pragma unroll
        for (int i = 0; i < 8; ++i)
            #pragma unroll
            for (int j = 0; j < 8; ++j)
                acc[i][j] += a[i] * b[j];
    }

    // Store to padded g_buf0 (rows >= NN land in pad, never read)
    float4* O4 = (float4*)g_buf0;
    #pragma unroll
    for (int i = 0; i < 8; ++i) {
        int row = row0 + ty * 8 + i;
        float4 o0 = {acc[i][0], acc[i][1], acc[i][2], acc[i][3]};
        float4 o1 = {acc[i][4], acc[i][5], acc[i][6], acc[i][7]};
        O4[(size_t)row * 32 + tx * 2]     = o0;
        O4[(size_t)row * 32 + tx * 2 + 1] = o1;
    }
}

// ---------------- Aggregation: warp per node, float4 per lane ----------------
__global__ void k_agg(const float* __restrict__ bias) {
    int gw = (blockIdx.x * blockDim.x + threadIdx.x) >> 5;
    int lane = threadIdx.x & 31;
    if (gw >= NN) return;
    const float4* __restrict__ H4 = (const float4*)g_buf0;

    float di = g_dinv[gw];
    float w0 = di * di;                           // self-loop norm
    float4 h = H4[(size_t)gw * 32 + lane];
    float4 acc = {h.x * w0, h.y * w0, h.z * w0, h.w * w0};

    int beg = g_off[gw], end = g_off[gw + 1];
    #pragma unroll 4
    for (int j = beg; j < end; ++j) {
        int s = g_esrc[j];
        float w = g_enorm[j];
        float4 v = H4[(size_t)s * 32 + lane];
        acc.x += w * v.x; acc.y += w * v.y; acc.z += w * v.z; acc.w += w * v.w;
    }
    float4 b = ((const float4*)bias)[lane];
    acc.x = fmaxf(acc.x + b.x, 0.0f);
    acc.y = fmaxf(acc.y + b.y, 0.0f);
    acc.z = fmaxf(acc.z + b.z, 0.0f);
    acc.w = fmaxf(acc.w + b.w, 0.0f);
    ((float4*)g_buf1)[(size_t)gw * 32 + lane] = acc;
}

// Second aggregation fused with final linear: out[i] = relu(agg+b2) . Wlin + blin
__global__ void k_agg_final(const float* __restrict__ bias,
                            const float* __restrict__ Wlin,
                            const float* __restrict__ blin,
                            float* __restrict__ out) {
    int gw = (blockIdx.x * blockDim.x + threadIdx.x) >> 5;
    int lane = threadIdx.x & 31;
    if (gw >= NN) return;
    const float4* __restrict__ H4 = (const float4*)g_buf0;

    float di = g_dinv[gw];
    float w0 = di * di;
    float4 h = H4[(size_t)gw * 32 + lane];
    float4 acc = {h.x * w0, h.y * w0, h.z * w0, h.w * w0};

    int beg = g_off[gw], end = g_off[gw + 1];
    #pragma unroll 4
    for (int j = beg; j < end; ++j) {
        int s = g_esrc[j];
        float w = g_enorm[j];
        float4 v = H4[(size_t)s * 32 + lane];
        acc.x += w * v.x; acc.y += w * v.y; acc.z += w * v.z; acc.w += w * v.w;
    }
    float4 b = ((const float4*)bias)[lane];
    acc.x = fmaxf(acc.x + b.x, 0.0f);
    acc.y = fmaxf(acc.y + b.y, 0.0f);
    acc.z = fmaxf(acc.z + b.z, 0.0f);
    acc.w = fmaxf(acc.w + b.w, 0.0f);

    float4 wl = ((const float4*)Wlin)[lane];
    float s4 = acc.x * wl.x + acc.y * wl.y + acc.z * wl.z + acc.w * wl.w;
    #pragma unroll
    for (int o = 16; o; o >>= 1) s4 += __shfl_xor_sync(0xFFFFFFFFu, s4, o);
    if (lane == 0) out[gw] = s4 + blin[0];
}

// ---------------- launch ----------------
extern "C" void kernel_launch(void* const* d_in, const int* in_sizes, int n_in,
                              void* d_out, int out_size) {
    const float* x  = (const float*)d_in[0];
    const void*  ei = d_in[2];
    // num_nodes may or may not be materialized as an input; find W1 by size.
    int base = (in_sizes[3] == C * C) ? 3 : 4;
    const float* W1   = (const float*)d_in[base + 0];
    const float* b1   = (const float*)d_in[base + 1];
    const float* W2   = (const float*)d_in[base + 2];
    const float* b2   = (const float*)d_in[base + 3];
    const float* Wlin = (const float*)d_in[base + 4];
    const float* blin = (const float*)d_in[base + 5];
    float* out = (float*)d_out;
    (void)n_in; (void)out_size;

    cudaFuncSetAttribute(k_gemm2, cudaFuncAttributeMaxDynamicSharedMemorySize,
                         GEMM_SMEM_BYTES);

    k_probe<<<1, 32>>>((const unsigned int*)ei);
    k_init<<<(NN + 255) / 256, 256>>>();
    k_count<<<(NE + 255) / 256, 256>>>(ei);
    k_dinv<<<(NN + 255) / 256, 256>>>();
    k_scan<<<1, 1024>>>();
    k_fill<<<(NE + 255) / 256, 256>>>(ei);

    const int gemm_blocks = M_PAD / 128;   // 391
    // Layer 1
    k_gemm2<<<gemm_blocks, 256, GEMM_SMEM_BYTES>>>(x, W1);
    k_agg<<<(NN * 32 + 255) / 256, 256>>>(b1);
    // Layer 2 (reads g_buf1, writes g_buf0)
    k_gemm2<<<gemm_blocks, 256, GEMM_SMEM_BYTES>>>(nullptr, W2);
    k_agg_final<<<(NN * 32 + 255) / 256, 256>>>(b2, Wlin, blin, out);
}

// round 3
// speedup vs baseline: 1.1517x; 1.1517x over previous
#include <cuda_runtime.h>
#include <cuda_fp16.h>
#include <cuda_bf16.h>
#include <cstdint>

#define NN 50000
#define NE 800000
#define C 128
#define M_PAD 50048   /* 391 * 128 */

#define PKW 68        /* u32 pitch of one bf16 tile row (136 bf16 = 272 B) */
#define IMG_U32 (128 * PKW)          /* 8704 u32 per 128x128 bf16 image */
#define IMG_BYTES (IMG_U32 * 4)      /* 34816 B */
#define SM_TOTAL (4 * IMG_BYTES)     /* Ahi, Alo, Whi, Wlo = 139264 B */

// ---------------- device scratch (static, no allocation) ----------------
__device__ int      g_is64;
__device__ int      g_deg[NN];
__device__ int      g_cursor[NN];
__device__ int      g_off[NN + 1];
__device__ float    g_dinv[NN];
__device__ int      g_esrc[NE];
__device__ float    g_enorm[NE];
__device__ __half   g_h[(size_t)M_PAD * C];     // GEMM output (fp16 gather table)
__device__ float    g_buf1[(size_t)M_PAD * C];  // aggregated activations (fp32)
// W images: [W1hi, W1lo, W2hi, W2lo]; row-major n x k bf16, pitch PKW u32.
__device__ uint32_t g_Wimg[4][IMG_U32];

// ---------------- small helpers ----------------
__device__ __forceinline__ uint32_t smem_u32(const void* p) {
    uint32_t a;
    asm("{ .reg .u64 t; cvta.to.shared.u64 t, %1; cvt.u32.u64 %0, t; }" : "=r"(a) : "l"(p));
    return a;
}
__device__ __forceinline__ uint32_t pack_bf16(float lo_elem, float hi_elem) {
    __nv_bfloat162 t = __floats2bfloat162_rn(lo_elem, hi_elem);  // .x = first arg
    return *reinterpret_cast<uint32_t*>(&t);
}
__device__ __forceinline__ void ldsm_x4(uint32_t* r, uint32_t addr) {
    asm volatile("ldmatrix.sync.aligned.m8n8.x4.shared.b16 {%0,%1,%2,%3}, [%4];"
                 : "=r"(r[0]), "=r"(r[1]), "=r"(r[2]), "=r"(r[3]) : "r"(addr));
}
__device__ __forceinline__ void mma_bf16(float* c, const uint32_t* a, uint32_t b0, uint32_t b1) {
    asm volatile(
        "mma.sync.aligned.m16n8k16.row.col.f32.bf16.bf16.f32 "
        "{%0,%1,%2,%3}, {%4,%5,%6,%7}, {%8,%9}, {%0,%1,%2,%3};"
        : "+f"(c[0]), "+f"(c[1]), "+f"(c[2]), "+f"(c[3])
        : "r"(a[0]), "r"(a[1]), "r"(a[2]), "r"(a[3]), "r"(b0), "r"(b1));
}

// ---------------- dtype probe: int64 vs int32 edge_index ----------------
// Values < 50000 fit in 16 bits, so for int64 data every odd u32 word is 0.
// For int32 data the odd words are actual edge ids (nonzero w.h.p. over 1024).
__global__ void k_probe(const unsigned int* __restrict__ w) {
    int lane = threadIdx.x;
    unsigned int acc = 0;
    #pragma unroll
    for (int i = 0; i < 32; ++i) acc |= w[2 * (lane + 32 * i) + 1];
    int any = __any_sync(0xFFFFFFFFu, acc != 0);
    if (lane == 0) g_is64 = !any;
}
__device__ __forceinline__ int edge_at(const void* ei, int is64, long long idx) {
    return is64 ? (int)((const long long*)ei)[idx] : ((const int*)ei)[idx];
}

// ---------------- CSR construction ----------------
__global__ void k_init() {
    int i = blockIdx.x * blockDim.x + threadIdx.x;
    if (i < NN) { g_deg[i] = 0; g_cursor[i] = 0; }
}
__global__ void k_count(const void* __restrict__ ei) {
    int e = blockIdx.x * blockDim.x + threadIdx.x;
    if (e >= NE) return;
    atomicAdd(&g_deg[edge_at(ei, g_is64, (long long)NE + e)], 1);
}
// exclusive-prefix over degrees + dinv, single 1024-thread block
__global__ void k_scan() {
    __shared__ int ps[1024];
    int t = threadIdx.x;
    const int CH = (NN + 1023) / 1024;
    int lo = t * CH, hi = lo + CH; if (hi > NN) hi = NN;
    int sum = 0;
    for (int i = lo; i < hi; ++i) {
        int d = g_deg[i];
        g_dinv[i] = rsqrtf((float)(d + 1));   // +1 self loop
        sum += d;
    }
    ps[t] = sum;
    __syncthreads();
    for (int off = 1; off < 1024; off <<= 1) {
        int v = (t >= off) ? ps[t - off] : 0;
        __syncthreads();
        ps[t] += v;
        __syncthreads();
    }
    int run = (t == 0) ? 0 : ps[t - 1];
    for (int i = lo; i < hi; ++i) { g_off[i] = run; run += g_deg[i]; }
    if (t == 1023) g_off[NN] = ps[1023];
}
__global__ void k_fill(const void* __restrict__ ei) {
    int e = blockIdx.x * blockDim.x + threadIdx.x;
    if (e >= NE) return;
    int is64 = g_is64;
    int s = edge_at(ei, is64, e);
    int d = edge_at(ei, is64, (long long)NE + e);
    int pos = g_off[d] + atomicAdd(&g_cursor[d], 1);
    g_esrc[pos]  = s;
    g_enorm[pos] = g_dinv[s] * g_dinv[d];
}

// ---------------- W prep: transpose + bf16 hi/lo split ----------------
// Image row n holds Bt[n][k] = W[k][n] (row-major n x k), so MMA gives A @ W.
__global__ void k_prepW(const float* __restrict__ W1, const float* __restrict__ W2) {
    int idx = blockIdx.x * blockDim.x + threadIdx.x;   // 0..16383
    if (idx >= 16384) return;
    int m  = idx >> 13;
    int p  = idx & 8191;
    int n  = p >> 6;               // output channel = image row
    int kp = p & 63;               // k-pair
    const float* W = m ? W2 : W1;
    float v0 = W[(2 * kp) * C + n];
    float v1 = W[(2 * kp + 1) * C + n];
    float h0 = __bfloat162float(__float2bfloat16_rn(v0));
    float h1 = __bfloat162float(__float2bfloat16_rn(v1));
    g_Wimg[m * 2 + 0][n * PKW + kp] = pack_bf16(h0, h1);
    g_Wimg[m * 2 + 1][n * PKW + kp] = pack_bf16(v0 - h0, v1 - h1);
}

// ---------------- HMMA GEMM: g_h[tile] = A @ W (bf16x2 split, fp32 acc) -----
// CTA: 256 thr, tile 128 rows x 128 cols, K=128. Warp tile 64x32 (2x4 warps).
__global__ void __launch_bounds__(256, 1) k_gemm(const float* __restrict__ Aext, int wsel) {
    extern __shared__ char smem[];
    uint32_t* Ahi = (uint32_t*)smem;
    uint32_t* Alo = Ahi + IMG_U32;
    const uint32_t sb = smem_u32(smem);
    const int tid = threadIdx.x;
    const int row0 = blockIdx.x * 128;
    const float* __restrict__ A = Aext ? Aext : g_buf1;

    // --- load A tile (coalesced float2), split to bf16 hi/lo ---
    #pragma unroll
    for (int i = 0; i < 32; ++i) {
        int p  = tid + 256 * i;        // 0..8191
        int r  = p >> 6;
        int kp = p & 63;
        int grow = row0 + r;
        float2 v = make_float2(0.f, 0.f);
        if (grow < NN) v = ((const float2*)A)[(size_t)grow * 64 + kp];
        float h0 = __bfloat162float(__float2bfloat16_rn(v.x));
        float h1 = __bfloat162float(__float2bfloat16_rn(v.y));
        Ahi[r * PKW + kp] = pack_bf16(h0, h1);
        Alo[r * PKW + kp] = pack_bf16(v.x - h0, v.y - h1);
    }
    // --- flat-copy W images (hi, lo) ---
    {
        const uint4* sh = (const uint4*)g_Wimg[wsel * 2 + 0];
        const uint4* sl = (const uint4*)g_Wimg[wsel * 2 + 1];
        uint4* dh = (uint4*)(smem + 2 * IMG_BYTES);
        uint4* dl = (uint4*)(smem + 3 * IMG_BYTES);
        #pragma unroll
        for (int i = 0; i < 9; ++i) {
            int x = tid + 256 * i;     // 0..2175 uint4
            if (x < IMG_BYTES / 16) { dh[x] = sh[x]; dl[x] = sl[x]; }
        }
    }
    __syncthreads();

    const int wid  = tid >> 5;
    const int lane = tid & 31;
    const int rm = (wid & 1) * 64;     // warp row base
    const int nb = (wid >> 1) * 32;    // warp col base

    // ldmatrix source addresses (byte offsets within an image)
    const int row_off = (lane & 7) + ((lane >> 3) & 1) * 8;
    const int kqA = lane >> 4;                       // 0/1 -> k quad
    uint32_t ao[4];
    #pragma unroll
    for (int mi = 0; mi < 4; ++mi)
        ao[mi] = ((rm + mi * 16 + row_off) * PKW + kqA * 4) * 4;
    const int n_off = (lane & 7) + ((lane & 16) ? 8 : 0);
    const int kqB = (lane >> 3) & 1;
    uint32_t bo[2];
    #pragma unroll
    for (int ni2 = 0; ni2 < 2; ++ni2)
        bo[ni2] = ((nb + ni2 * 16 + n_off) * PKW + kqB * 4) * 4;

    float acc[4][4][4];
    #pragma unroll
    for (int mi = 0; mi < 4; ++mi)
        #pragma unroll
        for (int ni = 0; ni < 4; ++ni)
            #pragma unroll
            for (int q = 0; q < 4; ++q) acc[mi][ni][q] = 0.0f;

    const uint32_t pa[3] = {0, 0, 1}, pb[3] = {0, 1, 0};
    #pragma unroll
    for (int pr = 0; pr < 3; ++pr) {
        uint32_t abase = sb + pa[pr] * IMG_BYTES;
        uint32_t bbase = sb + 2 * IMG_BYTES + pb[pr] * IMG_BYTES;
        #pragma unroll
        for (int ks = 0; ks < 8; ++ks) {
            uint32_t koff = ks * 32;   // 16 bf16 = 32 B
            uint32_t a[4][4], b[2][4];
            #pragma unroll
            for (int mi = 0; mi < 4; ++mi) ldsm_x4(a[mi], abase + ao[mi] + koff);
            #pragma unroll
            for (int ni2 = 0; ni2 < 2; ++ni2) ldsm_x4(b[ni2], bbase + bo[ni2] + koff);
            #pragma unroll
            for (int mi = 0; mi < 4; ++mi)
                #pragma unroll
                for (int ni = 0; ni < 4; ++ni)
                    mma_bf16(acc[mi][ni], a[mi],
                             b[ni >> 1][2 * (ni & 1)], b[ni >> 1][2 * (ni & 1) + 1]);
        }
    }

    // --- epilogue: fp16 store to gather table ---
    #pragma unroll
    for (int mi = 0; mi < 4; ++mi) {
        int row = row0 + rm + mi * 16 + (lane >> 2);
        #pragma unroll
        for (int ni = 0; ni < 4; ++ni) {
            int col = nb + ni * 8 + (lane & 3) * 2;
            __half2 lo = __float22half2_rn(make_float2(acc[mi][ni][0], acc[mi][ni][1]));
            __half2 hi = __float22half2_rn(make_float2(acc[mi][ni][2], acc[mi][ni][3]));
            *(__half2*)(g_h + (size_t)row * C + col)       = lo;
            *(__half2*)(g_h + (size_t)(row + 8) * C + col) = hi;
        }
    }
}

// ---------------- Aggregation: warp per node, 4 channels per lane ----------
__device__ __forceinline__ float4 gather_row(int row, int lane) {
    uint2 u = *(const uint2*)(g_h + (size_t)row * C + lane * 4);
    __half2 a = *(__half2*)&u.x, b = *(__half2*)&u.y;
    float2 f0 = __half22float2(a), f1 = __half22float2(b);
    return make_float4(f0.x, f0.y, f1.x, f1.y);
}

__global__ void k_agg(const float* __restrict__ bias) {
    int gw = (blockIdx.x * blockDim.x + threadIdx.x) >> 5;
    int lane = threadIdx.x & 31;
    if (gw >= NN) return;
    float di = g_dinv[gw];
    float w0 = di * di;
    float4 h = gather_row(gw, lane);
    float4 acc = {h.x * w0, h.y * w0, h.z * w0, h.w * w0};
    int beg = g_off[gw], end = g_off[gw + 1];
    #pragma unroll 4
    for (int j = beg; j < end; ++j) {
        int s = g_esrc[j];
        float w = g_enorm[j];
        float4 v = gather_row(s, lane);
        acc.x += w * v.x; acc.y += w * v.y; acc.z += w * v.z; acc.w += w * v.w;
    }
    float4 b = ((const float4*)bias)[lane];
    acc.x = fmaxf(acc.x + b.x, 0.0f);
    acc.y = fmaxf(acc.y + b.y, 0.0f);
    acc.z = fmaxf(acc.z + b.z, 0.0f);
    acc.w = fmaxf(acc.w + b.w, 0.0f);
    ((float4*)g_buf1)[(size_t)gw * 32 + lane] = acc;
}

__global__ void k_agg_final(const float* __restrict__ bias,
                            const float* __restrict__ Wlin,
                            const float* __restrict__ blin,
                            float* __restrict__ out) {
    int gw = (blockIdx.x * blockDim.x + threadIdx.x) >> 5;
    int lane = threadIdx.x & 31;
    if (gw >= NN) return;
    float di = g_dinv[gw];
    float w0 = di * di;
    float4 h = gather_row(gw, lane);
    float4 acc = {h.x * w0, h.y * w0, h.z * w0, h.w * w0};
    int beg = g_off[gw], end = g_off[gw + 1];
    #pragma unroll 4
    for (int j = beg; j < end; ++j) {
        int s = g_esrc[j];
        float w = g_enorm[j];
        float4 v = gather_row(s, lane);
        acc.x += w * v.x; acc.y += w * v.y; acc.z += w * v.z; acc.w += w * v.w;
    }
    float4 b = ((const float4*)bias)[lane];
    acc.x = fmaxf(acc.x + b.x, 0.0f);
    acc.y = fmaxf(acc.y + b.y, 0.0f);
    acc.z = fmaxf(acc.z + b.z, 0.0f);
    acc.w = fmaxf(acc.w + b.w, 0.0f);
    float4 wl = ((const float4*)Wlin)[lane];
    float s4 = acc.x * wl.x + acc.y * wl.y + acc.z * wl.z + acc.w * wl.w;
    #pragma unroll
    for (int o = 16; o; o >>= 1) s4 += __shfl_xor_sync(0xFFFFFFFFu, s4, o);
    if (lane == 0) out[gw] = s4 + blin[0];
}

// ---------------- launch ----------------
extern "C" void kernel_launch(void* const* d_in, const int* in_sizes, int n_in,
                              void* d_out, int out_size) {
    const float* x  = (const float*)d_in[0];
    const void*  ei = d_in[2];
    int base = (in_sizes[3] == C * C) ? 3 : 4;
    const float* W1   = (const float*)d_in[base + 0];
    const float* b1   = (const float*)d_in[base + 1];
    const float* W2   = (const float*)d_in[base + 2];
    const float* b2   = (const float*)d_in[base + 3];
    const float* Wlin = (const float*)d_in[base + 4];
    const float* blin = (const float*)d_in[base + 5];
    float* out = (float*)d_out;
    (void)n_in; (void)out_size;

    cudaFuncSetAttribute(k_gemm, cudaFuncAttributeMaxDynamicSharedMemorySize, SM_TOTAL);

    k_probe<<<1, 32>>>((const unsigned int*)ei);
    k_init<<<(NN + 255) / 256, 256>>>();
    k_count<<<(NE + 255) / 256, 256>>>(ei);
    k_scan<<<1, 1024>>>();
    k_fill<<<(NE + 255) / 256, 256>>>(ei);
    k_prepW<<<64, 256>>>(W1, W2);

    const int gemm_blocks = M_PAD / 128;   // 391
    k_gemm<<<gemm_blocks, 256, SM_TOTAL>>>(x, 0);
    k_agg<<<(NN * 32 + 255) / 256, 256>>>(b1);
    k_gemm<<<gemm_blocks, 256, SM_TOTAL>>>(nullptr, 1);
    k_agg_final<<<(NN * 32 + 255) / 256, 256>>>(b2, Wlin, blin, out);
}

// round 4
// speedup vs baseline: 1.8437x; 1.6008x over previous
#include <cuda_runtime.h>
#include <cuda_fp16.h>
#include <cuda_bf16.h>
#include <cstdint>

#define NN 50000
#define NE 800000
#define C 128
#define M_PAD 50048   /* 391 * 128 */
#define SCAN_B 196    /* ceil(NN/256) */

#define PKW 68        /* u32 pitch of one bf16 tile row (136 bf16 = 272 B) */
#define IMG_U32 (128 * PKW)          /* 8704 u32 per 128x128 bf16 image */
#define IMG_BYTES (IMG_U32 * 4)      /* 34816 B */
#define SM_TOTAL (4 * IMG_BYTES)     /* Ahi, Alo, Whi, Wlo = 139264 B */

// ---------------- device scratch (static, no allocation) ----------------
__device__ int      g_is64;
__device__ int      g_deg[NN];
__device__ int      g_cursor[NN];
__device__ int      g_off[NN + 1];
__device__ int      g_bsum[SCAN_B];
__device__ int      g_boff[SCAN_B];
__device__ float    g_dinv[NN];
__device__ uint2    g_edge[NE];                 // {src, norm-bits} packed
__device__ __half   g_h[(size_t)M_PAD * C];     // GEMM output (fp16 gather table)
__device__ float    g_buf1[(size_t)M_PAD * C];  // aggregated activations (fp32)
// W images: [W1hi, W1lo, W2hi, W2lo]; row-major n x k bf16, pitch PKW u32.
__device__ uint32_t g_Wimg[4][IMG_U32];

// ---------------- small helpers ----------------
__device__ __forceinline__ uint32_t smem_u32(const void* p) {
    uint32_t a;
    asm("{ .reg .u64 t; cvta.to.shared.u64 t, %1; cvt.u32.u64 %0, t; }" : "=r"(a) : "l"(p));
    return a;
}
__device__ __forceinline__ uint32_t pack_bf16(float lo_elem, float hi_elem) {
    __nv_bfloat162 t = __floats2bfloat162_rn(lo_elem, hi_elem);  // .x = first arg
    return *reinterpret_cast<uint32_t*>(&t);
}
__device__ __forceinline__ void ldsm_x4(uint32_t* r, uint32_t addr) {
    asm volatile("ldmatrix.sync.aligned.m8n8.x4.shared.b16 {%0,%1,%2,%3}, [%4];"
                 : "=r"(r[0]), "=r"(r[1]), "=r"(r[2]), "=r"(r[3]) : "r"(addr));
}
__device__ __forceinline__ void mma_bf16(float* c, const uint32_t* a, uint32_t b0, uint32_t b1) {
    asm volatile(
        "mma.sync.aligned.m16n8k16.row.col.f32.bf16.bf16.f32 "
        "{%0,%1,%2,%3}, {%4,%5,%6,%7}, {%8,%9}, {%0,%1,%2,%3};"
        : "+f"(c[0]), "+f"(c[1]), "+f"(c[2]), "+f"(c[3])
        : "r"(a[0]), "r"(a[1]), "r"(a[2]), "r"(a[3]), "r"(b0), "r"(b1));
}

// ---------------- dtype probe: int64 vs int32 edge_index ----------------
__global__ void k_probe(const unsigned int* __restrict__ w) {
    int lane = threadIdx.x;
    unsigned int acc = 0;
    #pragma unroll
    for (int i = 0; i < 32; ++i) acc |= w[2 * (lane + 32 * i) + 1];
    int any = __any_sync(0xFFFFFFFFu, acc != 0);
    if (lane == 0) g_is64 = !any;
}
__device__ __forceinline__ int edge_at(const void* ei, int is64, long long idx) {
    return is64 ? (int)((const long long*)ei)[idx] : ((const int*)ei)[idx];
}

// ---------------- CSR construction ----------------
__global__ void k_init() {
    int i = blockIdx.x * blockDim.x + threadIdx.x;
    if (i < NN) { g_deg[i] = 0; g_cursor[i] = 0; }
}
__global__ void k_count(const void* __restrict__ ei) {
    int e = blockIdx.x * blockDim.x + threadIdx.x;
    if (e >= NE) return;
    atomicAdd(&g_deg[edge_at(ei, g_is64, (long long)NE + e)], 1);
}

// scan stage 1: per-256-node block sum + dinv  (grid = SCAN_B)
__global__ void k_scan1() {
    __shared__ int ws[8];
    int i = blockIdx.x * 256 + threadIdx.x;
    int d = 0;
    if (i < NN) {
        d = g_deg[i];
        g_dinv[i] = rsqrtf((float)(d + 1));   // +1 self loop
    }
    int v = d;
    #pragma unroll
    for (int o = 16; o; o >>= 1) v += __shfl_xor_sync(0xFFFFFFFFu, v, o);
    if ((threadIdx.x & 31) == 0) ws[threadIdx.x >> 5] = v;
    __syncthreads();
    if (threadIdx.x == 0) {
        int s = 0;
        #pragma unroll
        for (int k = 0; k < 8; ++k) s += ws[k];
        g_bsum[blockIdx.x] = s;
    }
}
// scan stage 2: exclusive scan of SCAN_B block sums (one 256-thread block)
__global__ void k_scan2() {
    __shared__ int ps[256];
    int t = threadIdx.x;
    ps[t] = (t < SCAN_B) ? g_bsum[t] : 0;
    __syncthreads();
    #pragma unroll
    for (int off = 1; off < 256; off <<= 1) {
        int v = (t >= off) ? ps[t - off] : 0;
        __syncthreads();
        ps[t] += v;
        __syncthreads();
    }
    if (t < SCAN_B) g_boff[t] = (t == 0) ? 0 : ps[t - 1];
    if (t == 0) g_off[NN] = NE;   // total degree == NE by construction
}
// scan stage 3: local exclusive scan within block + global offset
__global__ void k_scan3() {
    __shared__ int ps[256];
    int t = threadIdx.x;
    int i = blockIdx.x * 256 + t;
    int d = (i < NN) ? g_deg[i] : 0;
    ps[t] = d;
    __syncthreads();
    #pragma unroll
    for (int off = 1; off < 256; off <<= 1) {
        int v = (t >= off) ? ps[t - off] : 0;
        __syncthreads();
        ps[t] += v;
        __syncthreads();
    }
    if (i < NN) g_off[i] = g_boff[blockIdx.x] + ps[t] - d;  // exclusive
}

__global__ void k_fill(const void* __restrict__ ei) {
    int e = blockIdx.x * blockDim.x + threadIdx.x;
    if (e >= NE) return;
    int is64 = g_is64;
    int s = edge_at(ei, is64, e);
    int d = edge_at(ei, is64, (long long)NE + e);
    int pos = g_off[d] + atomicAdd(&g_cursor[d], 1);
    float nw = g_dinv[s] * g_dinv[d];
    g_edge[pos] = make_uint2((unsigned)s, __float_as_uint(nw));
}

// ---------------- W prep: transpose + bf16 hi/lo split ----------------
__global__ void k_prepW(const float* __restrict__ W1, const float* __restrict__ W2) {
    int idx = blockIdx.x * blockDim.x + threadIdx.x;   // 0..16383
    if (idx >= 16384) return;
    int m  = idx >> 13;
    int p  = idx & 8191;
    int n  = p >> 6;               // output channel = image row
    int kp = p & 63;               // k-pair
    const float* W = m ? W2 : W1;
    float v0 = W[(2 * kp) * C + n];
    float v1 = W[(2 * kp + 1) * C + n];
    float h0 = __bfloat162float(__float2bfloat16_rn(v0));
    float h1 = __bfloat162float(__float2bfloat16_rn(v1));
    g_Wimg[m * 2 + 0][n * PKW + kp] = pack_bf16(h0, h1);
    g_Wimg[m * 2 + 1][n * PKW + kp] = pack_bf16(v0 - h0, v1 - h1);
}

// ---------------- HMMA GEMM: g_h[tile] = A @ W (bf16x2 split, fp32 acc) -----
__global__ void __launch_bounds__(256, 1) k_gemm(const float* __restrict__ Aext, int wsel) {
    extern __shared__ char smem[];
    uint32_t* Ahi = (uint32_t*)smem;
    uint32_t* Alo = Ahi + IMG_U32;
    const uint32_t sb = smem_u32(smem);
    const int tid = threadIdx.x;
    const int row0 = blockIdx.x * 128;
    const float* __restrict__ A = Aext ? Aext : g_buf1;

    #pragma unroll
    for (int i = 0; i < 32; ++i) {
        int p  = tid + 256 * i;        // 0..8191
        int r  = p >> 6;
        int kp = p & 63;
        int grow = row0 + r;
        float2 v = make_float2(0.f, 0.f);
        if (grow < NN) v = ((const float2*)A)[(size_t)grow * 64 + kp];
        float h0 = __bfloat162float(__float2bfloat16_rn(v.x));
        float h1 = __bfloat162float(__float2bfloat16_rn(v.y));
        Ahi[r * PKW + kp] = pack_bf16(h0, h1);
        Alo[r * PKW + kp] = pack_bf16(v.x - h0, v.y - h1);
    }
    {
        const uint4* sh = (const uint4*)g_Wimg[wsel * 2 + 0];
        const uint4* sl = (const uint4*)g_Wimg[wsel * 2 + 1];
        uint4* dh = (uint4*)(smem + 2 * IMG_BYTES);
        uint4* dl = (uint4*)(smem + 3 * IMG_BYTES);
        #pragma unroll
        for (int i = 0; i < 9; ++i) {
            int x = tid + 256 * i;     // 0..2175 uint4
            if (x < IMG_BYTES / 16) { dh[x] = sh[x]; dl[x] = sl[x]; }
        }
    }
    __syncthreads();

    const int wid  = tid >> 5;
    const int lane = tid & 31;
    const int rm = (wid & 1) * 64;     // warp row base
    const int nb = (wid >> 1) * 32;    // warp col base

    const int row_off = (lane & 7) + ((lane >> 3) & 1) * 8;
    const int kqA = lane >> 4;
    uint32_t ao[4];
    #pragma unroll
    for (int mi = 0; mi < 4; ++mi)
        ao[mi] = ((rm + mi * 16 + row_off) * PKW + kqA * 4) * 4;
    const int n_off = (lane & 7) + ((lane & 16) ? 8 : 0);
    const int kqB = (lane >> 3) & 1;
    uint32_t bo[2];
    #pragma unroll
    for (int ni2 = 0; ni2 < 2; ++ni2)
        bo[ni2] = ((nb + ni2 * 16 + n_off) * PKW + kqB * 4) * 4;

    float acc[4][4][4];
    #pragma unroll
    for (int mi = 0; mi < 4; ++mi)
        #pragma unroll
        for (int ni = 0; ni < 4; ++ni)
            #pragma unroll
            for (int q = 0; q < 4; ++q) acc[mi][ni][q] = 0.0f;

    const uint32_t pa[3] = {0, 0, 1}, pb[3] = {0, 1, 0};
    #pragma unroll
    for (int pr = 0; pr < 3; ++pr) {
        uint32_t abase = sb + pa[pr] * IMG_BYTES;
        uint32_t bbase = sb + 2 * IMG_BYTES + pb[pr] * IMG_BYTES;
        #pragma unroll
        for (int ks = 0; ks < 8; ++ks) {
            uint32_t koff = ks * 32;   // 16 bf16 = 32 B
            uint32_t a[4][4], b[2][4];
            #pragma unroll
            for (int mi = 0; mi < 4; ++mi) ldsm_x4(a[mi], abase + ao[mi] + koff);
            #pragma unroll
            for (int ni2 = 0; ni2 < 2; ++ni2) ldsm_x4(b[ni2], bbase + bo[ni2] + koff);
            #pragma unroll
            for (int mi = 0; mi < 4; ++mi)
                #pragma unroll
                for (int ni = 0; ni < 4; ++ni)
                    mma_bf16(acc[mi][ni], a[mi],
                             b[ni >> 1][2 * (ni & 1)], b[ni >> 1][2 * (ni & 1) + 1]);
        }
    }

    #pragma unroll
    for (int mi = 0; mi < 4; ++mi) {
        int row = row0 + rm + mi * 16 + (lane >> 2);
        #pragma unroll
        for (int ni = 0; ni < 4; ++ni) {
            int col = nb + ni * 8 + (lane & 3) * 2;
            __half2 lo = __float22half2_rn(make_float2(acc[mi][ni][0], acc[mi][ni][1]));
            __half2 hi = __float22half2_rn(make_float2(acc[mi][ni][2], acc[mi][ni][3]));
            *(__half2*)(g_h + (size_t)row * C + col)       = lo;
            *(__half2*)(g_h + (size_t)(row + 8) * C + col) = hi;
        }
    }
}

// ---------------- Aggregation: warp per node, 4 channels per lane ----------
__device__ __forceinline__ float4 gather_row(int row, int lane) {
    uint2 u = *(const uint2*)(g_h + (size_t)row * C + lane * 4);
    __half2 a = *(__half2*)&u.x, b = *(__half2*)&u.y;
    float2 f0 = __half22float2(a), f1 = __half22float2(b);
    return make_float4(f0.x, f0.y, f1.x, f1.y);
}

__global__ void k_agg(const float* __restrict__ bias) {
    int gw = (blockIdx.x * blockDim.x + threadIdx.x) >> 5;
    int lane = threadIdx.x & 31;
    if (gw >= NN) return;
    float di = g_dinv[gw];
    float w0 = di * di;
    float4 h = gather_row(gw, lane);
    float4 acc = {h.x * w0, h.y * w0, h.z * w0, h.w * w0};
    int beg = g_off[gw], end = g_off[gw + 1];
    #pragma unroll 4
    for (int j = beg; j < end; ++j) {
        uint2 e = g_edge[j];
        float w = __uint_as_float(e.y);
        float4 v = gather_row((int)e.x, lane);
        acc.x += w * v.x; acc.y += w * v.y; acc.z += w * v.z; acc.w += w * v.w;
    }
    float4 b = ((const float4*)bias)[lane];
    acc.x = fmaxf(acc.x + b.x, 0.0f);
    acc.y = fmaxf(acc.y + b.y, 0.0f);
    acc.z = fmaxf(acc.z + b.z, 0.0f);
    acc.w = fmaxf(acc.w + b.w, 0.0f);
    ((float4*)g_buf1)[(size_t)gw * 32 + lane] = acc;
}

__global__ void k_agg_final(const float* __restrict__ bias,
                            const float* __restrict__ Wlin,
                            const float* __restrict__ blin,
                            float* __restrict__ out) {
    int gw = (blockIdx.x * blockDim.x + threadIdx.x) >> 5;
    int lane = threadIdx.x & 31;
    if (gw >= NN) return;
    float di = g_dinv[gw];
    float w0 = di * di;
    float4 h = gather_row(gw, lane);
    float4 acc = {h.x * w0, h.y * w0, h.z * w0, h.w * w0};
    int beg = g_off[gw], end = g_off[gw + 1];
    #pragma unroll 4
    for (int j = beg; j < end; ++j) {
        uint2 e = g_edge[j];
        float w = __uint_as_float(e.y);
        float4 v = gather_row((int)e.x, lane);
        acc.x += w * v.x; acc.y += w * v.y; acc.z += w * v.z; acc.w += w * v.w;
    }
    float4 b = ((const float4*)bias)[lane];
    acc.x = fmaxf(acc.x + b.x, 0.0f);
    acc.y = fmaxf(acc.y + b.y, 0.0f);
    acc.z = fmaxf(acc.z + b.z, 0.0f);
    acc.w = fmaxf(acc.w + b.w, 0.0f);
    float4 wl = ((const float4*)Wlin)[lane];
    float s4 = acc.x * wl.x + acc.y * wl.y + acc.z * wl.z + acc.w * wl.w;
    #pragma unroll
    for (int o = 16; o; o >>= 1) s4 += __shfl_xor_sync(0xFFFFFFFFu, s4, o);
    if (lane == 0) out[gw] = s4 + blin[0];
}

// ---------------- launch ----------------
extern "C" void kernel_launch(void* const* d_in, const int* in_sizes, int n_in,
                              void* d_out, int out_size) {
    const float* x  = (const float*)d_in[0];
    const void*  ei = d_in[2];
    int base = (in_sizes[3] == C * C) ? 3 : 4;
    const float* W1   = (const float*)d_in[base + 0];
    const float* b1   = (const float*)d_in[base + 1];
    const float* W2   = (const float*)d_in[base + 2];
    const float* b2   = (const float*)d_in[base + 3];
    const float* Wlin = (const float*)d_in[base + 4];
    const float* blin = (const float*)d_in[base + 5];
    float* out = (float*)d_out;
    (void)n_in; (void)out_size;

    cudaFuncSetAttribute(k_gemm, cudaFuncAttributeMaxDynamicSharedMemorySize, SM_TOTAL);

    k_probe<<<1, 32>>>((const unsigned int*)ei);
    k_init<<<(NN + 255) / 256, 256>>>();
    k_count<<<(NE + 255) / 256, 256>>>(ei);
    k_scan1<<<SCAN_B, 256>>>();
    k_scan2<<<1, 256>>>();
    k_scan3<<<SCAN_B, 256>>>();
    k_fill<<<(NE + 255) / 256, 256>>>(ei);
    k_prepW<<<64, 256>>>(W1, W2);

    const int gemm_blocks = M_PAD / 128;   // 391
    k_gemm<<<gemm_blocks, 256, SM_TOTAL>>>(x, 0);
    k_agg<<<(NN * 32 + 255) / 256, 256>>>(b1);
    k_gemm<<<gemm_blocks, 256, SM_TOTAL>>>(nullptr, 1);
    k_agg_final<<<(NN * 32 + 255) / 256, 256>>>(b2, Wlin, blin, out);
}

// round 5
// speedup vs baseline: 1.9164x; 1.0394x over previous
#include <cuda_runtime.h>
#include <cuda_fp16.h>
#include <cuda_bf16.h>
#include <cstdint>

#define NN 50000
#define NE 800000
#define C 128
#define M_PAD 50048   /* 391 * 128 */
#define SCAN_B 196    /* ceil(NN/256) */

#define PKW 68        /* u32 pitch of one bf16 tile row (136 bf16 = 272 B) */
#define IMG_U32 (128 * PKW)          /* 8704 u32 per 128x128 bf16 image */
#define IMG_BYTES (IMG_U32 * 4)      /* 34816 B */
#define SM_TOTAL (4 * IMG_BYTES)     /* Ahi, Alo, Whi, Wlo = 139264 B */

// ---------------- device scratch (static, no allocation) ----------------
__device__ int      g_is64;
__device__ int      g_deg[NN];
__device__ int      g_cursor[NN];   // seeded with CSR offsets by k_scan23
__device__ int      g_off[NN + 1];
__device__ int      g_bsum[SCAN_B];
__device__ float    g_dinv[NN];
__device__ uint2    g_edge[NE];                 // {src, norm-bits} packed
__device__ __half   g_h[(size_t)M_PAD * C];     // GEMM output (fp16 gather table)
__device__ float    g_buf1[(size_t)M_PAD * C];  // aggregated activations (fp32)
// W images: [W1hi, W1lo, W2hi, W2lo]; row-major n x k bf16, pitch PKW u32.
__device__ uint32_t g_Wimg[4][IMG_U32];

// ---------------- small helpers ----------------
__device__ __forceinline__ uint32_t smem_u32(const void* p) {
    uint32_t a;
    asm("{ .reg .u64 t; cvta.to.shared.u64 t, %1; cvt.u32.u64 %0, t; }" : "=r"(a) : "l"(p));
    return a;
}
__device__ __forceinline__ uint32_t pack_bf16(float lo_elem, float hi_elem) {
    __nv_bfloat162 t = __floats2bfloat162_rn(lo_elem, hi_elem);  // .x = first arg
    return *reinterpret_cast<uint32_t*>(&t);
}
__device__ __forceinline__ void ldsm_x4(uint32_t* r, uint32_t addr) {
    asm volatile("ldmatrix.sync.aligned.m8n8.x4.shared.b16 {%0,%1,%2,%3}, [%4];"
                 : "=r"(r[0]), "=r"(r[1]), "=r"(r[2]), "=r"(r[3]) : "r"(addr));
}
__device__ __forceinline__ void mma_bf16(float* c, const uint32_t* a, uint32_t b0, uint32_t b1) {
    asm volatile(
        "mma.sync.aligned.m16n8k16.row.col.f32.bf16.bf16.f32 "
        "{%0,%1,%2,%3}, {%4,%5,%6,%7}, {%8,%9}, {%0,%1,%2,%3};"
        : "+f"(c[0]), "+f"(c[1]), "+f"(c[2]), "+f"(c[3])
        : "r"(a[0]), "r"(a[1]), "r"(a[2]), "r"(a[3]), "r"(b0), "r"(b1));
}
__device__ __forceinline__ int edge_at(const void* ei, int is64, long long idx) {
    return is64 ? (int)((const long long*)ei)[idx] : ((const int*)ei)[idx];
}

// ---------------- setup: dtype probe + deg clear + W prep (one launch) ------
// grid = SCAN_B (196) x 256 threads.
__global__ void k_setup(const unsigned int* __restrict__ ei_w,
                        const float* __restrict__ W1, const float* __restrict__ W2) {
    int t = threadIdx.x;
    int gid = blockIdx.x * 256 + t;

    // probe: block 0, warp 0 — int64 edge ids (<50000) have all-zero hi words
    if (blockIdx.x == 0 && t < 32) {
        unsigned int acc = 0;
        #pragma unroll
        for (int i = 0; i < 32; ++i) acc |= ei_w[2 * (t + 32 * i) + 1];
        int any = __any_sync(0xFFFFFFFFu, acc != 0);
        if (t == 0) g_is64 = !any;
    }
    // degree clear
    if (gid < NN) g_deg[gid] = 0;
    // W prep: transpose + bf16 hi/lo split; image row n holds W[k][n]
    if (gid < 16384) {
        int m  = gid >> 13;
        int p  = gid & 8191;
        int n  = p >> 6;               // output channel = image row
        int kp = p & 63;               // k-pair
        const float* W = m ? W2 : W1;
        float v0 = W[(2 * kp) * C + n];
        float v1 = W[(2 * kp + 1) * C + n];
        float h0 = __bfloat162float(__float2bfloat16_rn(v0));
        float h1 = __bfloat162float(__float2bfloat16_rn(v1));
        g_Wimg[m * 2 + 0][n * PKW + kp] = pack_bf16(h0, h1);
        g_Wimg[m * 2 + 1][n * PKW + kp] = pack_bf16(v0 - h0, v1 - h1);
    }
}

__global__ void k_count(const void* __restrict__ ei) {
    int e = blockIdx.x * blockDim.x + threadIdx.x;
    if (e >= NE) return;
    atomicAdd(&g_deg[edge_at(ei, g_is64, (long long)NE + e)], 1);
}

// scan stage 1: per-256-node block sum + dinv  (grid = SCAN_B)
__global__ void k_scan1() {
    __shared__ int ws[8];
    int i = blockIdx.x * 256 + threadIdx.x;
    int d = 0;
    if (i < NN) {
        d = g_deg[i];
        g_dinv[i] = rsqrtf((float)(d + 1));   // +1 self loop
    }
    int v = d;
    #pragma unroll
    for (int o = 16; o; o >>= 1) v += __shfl_xor_sync(0xFFFFFFFFu, v, o);
    if ((threadIdx.x & 31) == 0) ws[threadIdx.x >> 5] = v;
    __syncthreads();
    if (threadIdx.x == 0) {
        int s = 0;
        #pragma unroll
        for (int k = 0; k < 8; ++k) s += ws[k];
        g_bsum[blockIdx.x] = s;
    }
}

// scan stage 2+3 merged: every block redundantly scans the block sums (cheap),
// then local-scans its 256 degrees and writes offsets (also seeding cursors).
__global__ void k_scan23() {
    __shared__ int bs[256];
    __shared__ int ps[256];
    int t = threadIdx.x;
    int bid = blockIdx.x;

    bs[t] = (t < SCAN_B) ? g_bsum[t] : 0;
    __syncthreads();
    #pragma unroll
    for (int off = 1; off < 256; off <<= 1) {
        int v = (t >= off) ? bs[t - off] : 0;
        __syncthreads();
        bs[t] += v;
        __syncthreads();
    }
    int boff = (bid == 0) ? 0 : bs[bid - 1];

    int i = bid * 256 + t;
    int d = (i < NN) ? g_deg[i] : 0;
    ps[t] = d;
    __syncthreads();
    #pragma unroll
    for (int off = 1; off < 256; off <<= 1) {
        int v = (t >= off) ? ps[t - off] : 0;
        __syncthreads();
        ps[t] += v;
        __syncthreads();
    }
    if (i < NN) {
        int o = boff + ps[t] - d;   // exclusive
        g_off[i] = o;
        g_cursor[i] = o;
    }
    if (bid == 0 && t == 0) g_off[NN] = NE;   // total degree == NE
}

__global__ void k_fill(const void* __restrict__ ei) {
    int e = blockIdx.x * blockDim.x + threadIdx.x;
    if (e >= NE) return;
    int is64 = g_is64;
    int s = edge_at(ei, is64, e);
    int d = edge_at(ei, is64, (long long)NE + e);
    int pos = atomicAdd(&g_cursor[d], 1);   // cursor pre-seeded with offset
    float nw = g_dinv[s] * g_dinv[d];
    g_edge[pos] = make_uint2((unsigned)s, __float_as_uint(nw));
}

// ---------------- HMMA GEMM: g_h[tile] = A @ W (bf16x2 split, fp32 acc) -----
__global__ void __launch_bounds__(256, 1) k_gemm(const float* __restrict__ Aext, int wsel) {
    extern __shared__ char smem[];
    uint32_t* Ahi = (uint32_t*)smem;
    uint32_t* Alo = Ahi + IMG_U32;
    const uint32_t sb = smem_u32(smem);
    const int tid = threadIdx.x;
    const int row0 = blockIdx.x * 128;
    const float* __restrict__ A = Aext ? Aext : g_buf1;

    #pragma unroll
    for (int i = 0; i < 32; ++i) {
        int p  = tid + 256 * i;        // 0..8191
        int r  = p >> 6;
        int kp = p & 63;
        int grow = row0 + r;
        float2 v = make_float2(0.f, 0.f);
        if (grow < NN) v = ((const float2*)A)[(size_t)grow * 64 + kp];
        float h0 = __bfloat162float(__float2bfloat16_rn(v.x));
        float h1 = __bfloat162float(__float2bfloat16_rn(v.y));
        Ahi[r * PKW + kp] = pack_bf16(h0, h1);
        Alo[r * PKW + kp] = pack_bf16(v.x - h0, v.y - h1);
    }
    {
        const uint4* sh = (const uint4*)g_Wimg[wsel * 2 + 0];
        const uint4* sl = (const uint4*)g_Wimg[wsel * 2 + 1];
        uint4* dh = (uint4*)(smem + 2 * IMG_BYTES);
        uint4* dl = (uint4*)(smem + 3 * IMG_BYTES);
        #pragma unroll
        for (int i = 0; i < 9; ++i) {
            int x = tid + 256 * i;     // 0..2175 uint4
            if (x < IMG_BYTES / 16) { dh[x] = sh[x]; dl[x] = sl[x]; }
        }
    }
    __syncthreads();

    const int wid  = tid >> 5;
    const int lane = tid & 31;
    const int rm = (wid & 1) * 64;     // warp row base
    const int nb = (wid >> 1) * 32;    // warp col base

    const int row_off = (lane & 7) + ((lane >> 3) & 1) * 8;
    const int kqA = lane >> 4;
    uint32_t ao[4];
    #pragma unroll
    for (int mi = 0; mi < 4; ++mi)
        ao[mi] = ((rm + mi * 16 + row_off) * PKW + kqA * 4) * 4;
    const int n_off = (lane & 7) + ((lane & 16) ? 8 : 0);
    const int kqB = (lane >> 3) & 1;
    uint32_t bo[2];
    #pragma unroll
    for (int ni2 = 0; ni2 < 2; ++ni2)
        bo[ni2] = ((nb + ni2 * 16 + n_off) * PKW + kqB * 4) * 4;

    float acc[4][4][4];
    #pragma unroll
    for (int mi = 0; mi < 4; ++mi)
        #pragma unroll
        for (int ni = 0; ni < 4; ++ni)
            #pragma unroll
            for (int q = 0; q < 4; ++q) acc[mi][ni][q] = 0.0f;

    const uint32_t pa[3] = {0, 0, 1}, pb[3] = {0, 1, 0};
    #pragma unroll
    for (int pr = 0; pr < 3; ++pr) {
        uint32_t abase = sb + pa[pr] * IMG_BYTES;
        uint32_t bbase = sb + 2 * IMG_BYTES + pb[pr] * IMG_BYTES;
        #pragma unroll
        for (int ks = 0; ks < 8; ++ks) {
            uint32_t koff = ks * 32;   // 16 bf16 = 32 B
            uint32_t a[4][4], b[2][4];
            #pragma unroll
            for (int mi = 0; mi < 4; ++mi) ldsm_x4(a[mi], abase + ao[mi] + koff);
            #pragma unroll
            for (int ni2 = 0; ni2 < 2; ++ni2) ldsm_x4(b[ni2], bbase + bo[ni2] + koff);
            #pragma unroll
            for (int mi = 0; mi < 4; ++mi)
                #pragma unroll
                for (int ni = 0; ni < 4; ++ni)
                    mma_bf16(acc[mi][ni], a[mi],
                             b[ni >> 1][2 * (ni & 1)], b[ni >> 1][2 * (ni & 1) + 1]);
        }
    }

    #pragma unroll
    for (int mi = 0; mi < 4; ++mi) {
        int row = row0 + rm + mi * 16 + (lane >> 2);
        #pragma unroll
        for (int ni = 0; ni < 4; ++ni) {
            int col = nb + ni * 8 + (lane & 3) * 2;
            __half2 lo = __float22half2_rn(make_float2(acc[mi][ni][0], acc[mi][ni][1]));
            __half2 hi = __float22half2_rn(make_float2(acc[mi][ni][2], acc[mi][ni][3]));
            *(__half2*)(g_h + (size_t)row * C + col)       = lo;
            *(__half2*)(g_h + (size_t)(row + 8) * C + col) = hi;
        }
    }
}

// ---------------- Aggregation: warp per node, 4 channels per lane ----------
__device__ __forceinline__ float4 gather_row(int row, int lane) {
    uint2 u = *(const uint2*)(g_h + (size_t)row * C + lane * 4);
    __half2 a = *(__half2*)&u.x, b = *(__half2*)&u.y;
    float2 f0 = __half22float2(a), f1 = __half22float2(b);
    return make_float4(f0.x, f0.y, f1.x, f1.y);
}

__global__ void k_agg(const float* __restrict__ bias) {
    int gw = (blockIdx.x * blockDim.x + threadIdx.x) >> 5;
    int lane = threadIdx.x & 31;
    if (gw >= NN) return;
    float di = g_dinv[gw];
    float w0 = di * di;
    float4 h = gather_row(gw, lane);
    float4 acc = {h.x * w0, h.y * w0, h.z * w0, h.w * w0};
    int beg = g_off[gw], end = g_off[gw + 1];
    #pragma unroll 4
    for (int j = beg; j < end; ++j) {
        uint2 e = g_edge[j];
        float w = __uint_as_float(e.y);
        float4 v = gather_row((int)e.x, lane);
        acc.x += w * v.x; acc.y += w * v.y; acc.z += w * v.z; acc.w += w * v.w;
    }
    float4 b = ((const float4*)bias)[lane];
    acc.x = fmaxf(acc.x + b.x, 0.0f);
    acc.y = fmaxf(acc.y + b.y, 0.0f);
    acc.z = fmaxf(acc.z + b.z, 0.0f);
    acc.w = fmaxf(acc.w + b.w, 0.0f);
    ((float4*)g_buf1)[(size_t)gw * 32 + lane] = acc;
}

__global__ void k_agg_final(const float* __restrict__ bias,
                            const float* __restrict__ Wlin,
                            const float* __restrict__ blin,
                            float* __restrict__ out) {
    int gw = (blockIdx.x * blockDim.x + threadIdx.x) >> 5;
    int lane = threadIdx.x & 31;
    if (gw >= NN) return;
    float di = g_dinv[gw];
    float w0 = di * di;
    float4 h = gather_row(gw, lane);
    float4 acc = {h.x * w0, h.y * w0, h.z * w0, h.w * w0};
    int beg = g_off[gw], end = g_off[gw + 1];
    #pragma unroll 4
    for (int j = beg; j < end; ++j) {
        uint2 e = g_edge[j];
        float w = __uint_as_float(e.y);
        float4 v = gather_row((int)e.x, lane);
        acc.x += w * v.x; acc.y += w * v.y; acc.z += w * v.z; acc.w += w * v.w;
    }
    float4 b = ((const float4*)bias)[lane];
    acc.x = fmaxf(acc.x + b.x, 0.0f);
    acc.y = fmaxf(acc.y + b.y, 0.0f);
    acc.z = fmaxf(acc.z + b.z, 0.0f);
    acc.w = fmaxf(acc.w + b.w, 0.0f);
    float4 wl = ((const float4*)Wlin)[lane];
    float s4 = acc.x * wl.x + acc.y * wl.y + acc.z * wl.z + acc.w * wl.w;
    #pragma unroll
    for (int o = 16; o; o >>= 1) s4 += __shfl_xor_sync(0xFFFFFFFFu, s4, o);
    if (lane == 0) out[gw] = s4 + blin[0];
}

// ---------------- launch ----------------
extern "C" void kernel_launch(void* const* d_in, const int* in_sizes, int n_in,
                              void* d_out, int out_size) {
    const float* x  = (const float*)d_in[0];
    const void*  ei = d_in[2];
    int base = (in_sizes[3] == C * C) ? 3 : 4;
    const float* W1   = (const float*)d_in[base + 0];
    const float* b1   = (const float*)d_in[base + 1];
    const float* W2   = (const float*)d_in[base + 2];
    const float* b2   = (const float*)d_in[base + 3];
    const float* Wlin = (const float*)d_in[base + 4];
    const float* blin = (const float*)d_in[base + 5];
    float* out = (float*)d_out;
    (void)n_in; (void)out_size;

    cudaFuncSetAttribute(k_gemm, cudaFuncAttributeMaxDynamicSharedMemorySize, SM_TOTAL);

    k_setup<<<SCAN_B, 256>>>((const unsigned int*)ei, W1, W2);
    k_count<<<(NE + 255) / 256, 256>>>(ei);
    k_scan1<<<SCAN_B, 256>>>();
    k_scan23<<<SCAN_B, 256>>>();
    k_fill<<<(NE + 255) / 256, 256>>>(ei);

    const int gemm_blocks = M_PAD / 128;   // 391
    k_gemm<<<gemm_blocks, 256, SM_TOTAL>>>(x, 0);
    k_agg<<<(NN * 32 + 255) / 256, 256>>>(b1);
    k_gemm<<<gemm_blocks, 256, SM_TOTAL>>>(nullptr, 1);
    k_agg_final<<<(NN * 32 + 255) / 256, 256>>>(b2, Wlin, blin, out);
}